// round 12
// baseline (speedup 1.0000x reference)
#include <cuda_runtime.h>
#include <cuda_bf16.h>
#include <cstdint>

// LeftPool: out[b,c,h,w] = max(x[b,c,h,w:]) — reverse cummax along width (=128, contiguous).
//
// Persistent-CTA variant of the best-known config: 592 CTAs (148 SMs x 4),
// each warp grid-strides over work chunks. Per chunk: 4 rows strided by
// q = nrows/4 (4 independent 64MB-apart streams -> spreads requests across
// LTS slices / HBM channels; verified best in R10). Front-batched float4
// loads (MLP=4/thread); 4 independent suffix-scan chains hide SHFL latency.
// No wave transitions, no CTA relaunch between chunks.

__global__ void __launch_bounds__(512) leftpool_kernel(
    const float4* __restrict__ x, float4* __restrict__ out, int q)
{
    const int lane   = threadIdx.x & 31;
    const int warp0  = (int)((blockIdx.x * blockDim.x + threadIdx.x) >> 5);
    const int nwarps = (int)((gridDim.x * blockDim.x) >> 5);
    const size_t stride = (size_t)q * 32;
    const float ninf = __int_as_float(0xff800000u);

    for (int g = warp0; g < q; g += nwarps) {
        const size_t b0 = (size_t)g * 32 + lane;     // float4 index, row g
        const size_t b1 = b0 + stride;
        const size_t b2 = b1 + stride;
        const size_t b3 = b2 + stride;

        // Front-batch all loads before any dependent work.
        float4 v0 = x[b0];
        float4 v1 = x[b1];
        float4 v2 = x[b2];
        float4 v3 = x[b3];

        // In-lane suffix max (4 independent chains).
        v0.z = fmaxf(v0.z, v0.w);  v1.z = fmaxf(v1.z, v1.w);
        v2.z = fmaxf(v2.z, v2.w);  v3.z = fmaxf(v3.z, v3.w);
        v0.y = fmaxf(v0.y, v0.z);  v1.y = fmaxf(v1.y, v1.z);
        v2.y = fmaxf(v2.y, v2.z);  v3.y = fmaxf(v3.y, v3.z);
        v0.x = fmaxf(v0.x, v0.y);  v1.x = fmaxf(v1.x, v1.y);
        v2.x = fmaxf(v2.x, v2.y);  v3.x = fmaxf(v3.x, v3.y);

        // Inclusive suffix max across lanes; 4 chains in parallel.
        float m0 = v0.x, m1 = v1.x, m2 = v2.x, m3 = v3.x;
        #pragma unroll
        for (int d = 1; d < 32; d <<= 1) {
            float t0 = __shfl_down_sync(0xffffffffu, m0, d);
            float t1 = __shfl_down_sync(0xffffffffu, m1, d);
            float t2 = __shfl_down_sync(0xffffffffu, m2, d);
            float t3 = __shfl_down_sync(0xffffffffu, m3, d);
            m0 = fmaxf(m0, t0);   // out-of-range shfl returns own value -> harmless
            m1 = fmaxf(m1, t1);
            m2 = fmaxf(m2, t2);
            m3 = fmaxf(m3, t3);
        }
        // Exclusive suffix: shift down by one; lane 31 sees -inf.
        float s0 = __shfl_down_sync(0xffffffffu, m0, 1);
        float s1 = __shfl_down_sync(0xffffffffu, m1, 1);
        float s2 = __shfl_down_sync(0xffffffffu, m2, 1);
        float s3 = __shfl_down_sync(0xffffffffu, m3, 1);
        if (lane == 31) { s0 = ninf; s1 = ninf; s2 = ninf; s3 = ninf; }

        v0.x = fmaxf(v0.x, s0);  v1.x = fmaxf(v1.x, s1);
        v2.x = fmaxf(v2.x, s2);  v3.x = fmaxf(v3.x, s3);
        v0.y = fmaxf(v0.y, s0);  v1.y = fmaxf(v1.y, s1);
        v2.y = fmaxf(v2.y, s2);  v3.y = fmaxf(v3.y, s3);
        v0.z = fmaxf(v0.z, s0);  v1.z = fmaxf(v1.z, s1);
        v2.z = fmaxf(v2.z, s2);  v3.z = fmaxf(v3.z, s3);
        v0.w = fmaxf(v0.w, s0);  v1.w = fmaxf(v1.w, s1);
        v2.w = fmaxf(v2.w, s2);  v3.w = fmaxf(v3.w, s3);

        out[b0] = v0;
        out[b1] = v1;
        out[b2] = v2;
        out[b3] = v3;
    }
}

extern "C" void kernel_launch(void* const* d_in, const int* in_sizes, int n_in,
                              void* d_out, int out_size)
{
    const float* x = (const float*)d_in[0];
    float* out = (float*)d_out;

    const int W = 128;                          // contiguous width axis
    const int nrows = in_sizes[0] / W;          // 524288
    const int q = nrows / 4;                    // 131072 warp-chunks, 4 rows each

    const int threads = 512;                    // 16 warps/block
    const int blocks  = 592;                    // 148 SMs x 4 resident CTAs

    leftpool_kernel<<<blocks, threads>>>(
        (const float4*)x, (float4*)out, q);
}

// round 13
// speedup vs baseline: 1.0536x; 1.0536x over previous
#include <cuda_runtime.h>
#include <cuda_bf16.h>
#include <cstdint>

// LeftPool: out[b,c,h,w] = max(x[b,c,h,w:]) — reverse cummax along width (=128, contiguous).
//
// FINAL FORM (verified best across R4-R12 experiments):
//  - one warp per FOUR rows strided by q = nrows/4: 4 independent 64MB-apart
//    streams per warp spread requests across LTS slices / HBM channels
//    (consecutive-rows variant regressed DRAM 82.6% -> 77.2% in R10)
//  - front-batched float4 loads (MLP=4/thread) — ILP=2 -> +6% BW (R5),
//    ILP=4 saturates; the binder is the HBM R/W-stream ceiling ~6.5 TB/s
//  - 4 independent suffix-scan chains interleave to hide SHFL latency
//  - one-shot launch, 512-thread blocks, exact grid, 32 regs, full occupancy
//    (persistent grid-stride variant doubled regs -> occ 46% -> FAILED, R12;
//    streaming cache hints neutral, R6-R9)

__global__ void __launch_bounds__(512) leftpool_kernel(
    const float4* __restrict__ x, float4* __restrict__ out, int q)
{
    const int gwarp = (int)((blockIdx.x * blockDim.x + threadIdx.x) >> 5);
    const int lane  = threadIdx.x & 31;

    const size_t stride = (size_t)q * 32;
    const size_t b0 = (size_t)gwarp * 32 + lane;     // float4 index, row g
    const size_t b1 = b0 + stride;
    const size_t b2 = b1 + stride;
    const size_t b3 = b2 + stride;

    // Front-batch all loads before any dependent work.
    float4 v0 = x[b0];
    float4 v1 = x[b1];
    float4 v2 = x[b2];
    float4 v3 = x[b3];

    // In-lane suffix max (4 independent chains).
    v0.z = fmaxf(v0.z, v0.w);  v1.z = fmaxf(v1.z, v1.w);
    v2.z = fmaxf(v2.z, v2.w);  v3.z = fmaxf(v3.z, v3.w);
    v0.y = fmaxf(v0.y, v0.z);  v1.y = fmaxf(v1.y, v1.z);
    v2.y = fmaxf(v2.y, v2.z);  v3.y = fmaxf(v3.y, v3.z);
    v0.x = fmaxf(v0.x, v0.y);  v1.x = fmaxf(v1.x, v1.y);
    v2.x = fmaxf(v2.x, v2.y);  v3.x = fmaxf(v3.x, v3.y);

    // Inclusive suffix max across lanes; 4 chains in parallel.
    float m0 = v0.x, m1 = v1.x, m2 = v2.x, m3 = v3.x;
    #pragma unroll
    for (int d = 1; d < 32; d <<= 1) {
        float t0 = __shfl_down_sync(0xffffffffu, m0, d);
        float t1 = __shfl_down_sync(0xffffffffu, m1, d);
        float t2 = __shfl_down_sync(0xffffffffu, m2, d);
        float t3 = __shfl_down_sync(0xffffffffu, m3, d);
        m0 = fmaxf(m0, t0);   // out-of-range shfl returns own value -> harmless
        m1 = fmaxf(m1, t1);
        m2 = fmaxf(m2, t2);
        m3 = fmaxf(m3, t3);
    }
    // Exclusive suffix: shift down by one; lane 31 sees -inf.
    float s0 = __shfl_down_sync(0xffffffffu, m0, 1);
    float s1 = __shfl_down_sync(0xffffffffu, m1, 1);
    float s2 = __shfl_down_sync(0xffffffffu, m2, 1);
    float s3 = __shfl_down_sync(0xffffffffu, m3, 1);
    if (lane == 31) {
        const float ninf = __int_as_float(0xff800000u);
        s0 = ninf; s1 = ninf; s2 = ninf; s3 = ninf;
    }

    v0.x = fmaxf(v0.x, s0);  v1.x = fmaxf(v1.x, s1);
    v2.x = fmaxf(v2.x, s2);  v3.x = fmaxf(v3.x, s3);
    v0.y = fmaxf(v0.y, s0);  v1.y = fmaxf(v1.y, s1);
    v2.y = fmaxf(v2.y, s2);  v3.y = fmaxf(v3.y, s3);
    v0.z = fmaxf(v0.z, s0);  v1.z = fmaxf(v1.z, s1);
    v2.z = fmaxf(v2.z, s2);  v3.z = fmaxf(v3.z, s3);
    v0.w = fmaxf(v0.w, s0);  v1.w = fmaxf(v1.w, s1);
    v2.w = fmaxf(v2.w, s2);  v3.w = fmaxf(v3.w, s3);

    out[b0] = v0;
    out[b1] = v1;
    out[b2] = v2;
    out[b3] = v3;
}

extern "C" void kernel_launch(void* const* d_in, const int* in_sizes, int n_in,
                              void* d_out, int out_size)
{
    const float* x = (const float*)d_in[0];
    float* out = (float*)d_out;

    const int W = 128;                          // contiguous width axis
    const int nrows = in_sizes[0] / W;          // 524288
    const int q = nrows / 4;                    // 131072 warps, 4 rows each

    const int threads = 512;                    // 16 warps/block
    const int blocks = q / (threads / 32);      // 8192, divides exactly

    leftpool_kernel<<<blocks, threads>>>(
        (const float4*)x, (float4*)out, q);
}

// round 15
// speedup vs baseline: 1.0594x; 1.0055x over previous
#include <cuda_runtime.h>
#include <cuda_bf16.h>
#include <cstdint>

// LeftPool: out[b,c,h,w] = max(x[b,c,h,w:]) — reverse cummax along width (=128, contiguous).
//
// FINAL FORM — best-measured config across R4-R13 (R6 shape):
//  - one warp per FOUR rows strided by q = nrows/4: 4 independent 64MB-apart
//    streams per warp spread requests across LTS slices / HBM channels
//    (consecutive-rows variant regressed DRAM 82.6% -> 77.2%, R10)
//  - front-batched float4 loads (MLP=4/thread): ILP 1->2 gave +6% BW (R5,
//    reproduced); ILP=4 saturates at the HBM R/W-stream ceiling ~6.5 TB/s
//  - 4 independent suffix-scan chains interleave to hide SHFL latency (26cyc)
//  - 256-thread blocks, 16384 CTAs, 32 regs, ~80% occupancy
//  - rejected by experiment: streaming hints (neutral), persistent CTAs
//    (regs 32->64, occ 46%, -10% BW), 512-thread blocks (neutral)
//  - ncu metric deltas <6% on identical binaries are run-to-run noise (R13)

__global__ void __launch_bounds__(256) leftpool_kernel(
    const float4* __restrict__ x, float4* __restrict__ out, int q)
{
    const int gwarp = (int)((blockIdx.x * blockDim.x + threadIdx.x) >> 5);
    const int lane  = threadIdx.x & 31;
    if (gwarp >= q) return;

    const size_t stride = (size_t)q * 32;
    const size_t b0 = (size_t)gwarp * 32 + lane;     // float4 index, row g
    const size_t b1 = b0 + stride;
    const size_t b2 = b1 + stride;
    const size_t b3 = b2 + stride;

    // Front-batch all loads before any dependent work.
    float4 v0 = x[b0];
    float4 v1 = x[b1];
    float4 v2 = x[b2];
    float4 v3 = x[b3];

    // In-lane suffix max (4 independent chains).
    v0.z = fmaxf(v0.z, v0.w);  v1.z = fmaxf(v1.z, v1.w);
    v2.z = fmaxf(v2.z, v2.w);  v3.z = fmaxf(v3.z, v3.w);
    v0.y = fmaxf(v0.y, v0.z);  v1.y = fmaxf(v1.y, v1.z);
    v2.y = fmaxf(v2.y, v2.z);  v3.y = fmaxf(v3.y, v3.z);
    v0.x = fmaxf(v0.x, v0.y);  v1.x = fmaxf(v1.x, v1.y);
    v2.x = fmaxf(v2.x, v2.y);  v3.x = fmaxf(v3.x, v3.y);

    // Inclusive suffix max across lanes; 4 chains in parallel.
    float m0 = v0.x, m1 = v1.x, m2 = v2.x, m3 = v3.x;
    #pragma unroll
    for (int d = 1; d < 32; d <<= 1) {
        float t0 = __shfl_down_sync(0xffffffffu, m0, d);
        float t1 = __shfl_down_sync(0xffffffffu, m1, d);
        float t2 = __shfl_down_sync(0xffffffffu, m2, d);
        float t3 = __shfl_down_sync(0xffffffffu, m3, d);
        m0 = fmaxf(m0, t0);   // out-of-range shfl returns own value -> harmless
        m1 = fmaxf(m1, t1);
        m2 = fmaxf(m2, t2);
        m3 = fmaxf(m3, t3);
    }
    // Exclusive suffix: shift down by one; lane 31 sees -inf.
    float s0 = __shfl_down_sync(0xffffffffu, m0, 1);
    float s1 = __shfl_down_sync(0xffffffffu, m1, 1);
    float s2 = __shfl_down_sync(0xffffffffu, m2, 1);
    float s3 = __shfl_down_sync(0xffffffffu, m3, 1);
    if (lane == 31) {
        const float ninf = __int_as_float(0xff800000u);
        s0 = ninf; s1 = ninf; s2 = ninf; s3 = ninf;
    }

    v0.x = fmaxf(v0.x, s0);  v1.x = fmaxf(v1.x, s1);
    v2.x = fmaxf(v2.x, s2);  v3.x = fmaxf(v3.x, s3);
    v0.y = fmaxf(v0.y, s0);  v1.y = fmaxf(v1.y, s1);
    v2.y = fmaxf(v2.y, s2);  v3.y = fmaxf(v3.y, s3);
    v0.z = fmaxf(v0.z, s0);  v1.z = fmaxf(v1.z, s1);
    v2.z = fmaxf(v2.z, s2);  v3.z = fmaxf(v3.z, s3);
    v0.w = fmaxf(v0.w, s0);  v1.w = fmaxf(v1.w, s1);
    v2.w = fmaxf(v2.w, s2);  v3.w = fmaxf(v3.w, s3);

    out[b0] = v0;
    out[b1] = v1;
    out[b2] = v2;
    out[b3] = v3;
}

extern "C" void kernel_launch(void* const* d_in, const int* in_sizes, int n_in,
                              void* d_out, int out_size)
{
    const float* x = (const float*)d_in[0];
    float* out = (float*)d_out;

    const int W = 128;                          // contiguous width axis
    const int nrows = in_sizes[0] / W;          // 524288
    const int q = nrows / 4;                    // 131072 warps, 4 rows each

    const int threads = 256;                    // 8 warps/block
    const int warps_per_block = threads / 32;
    const int blocks = (q + warps_per_block - 1) / warps_per_block;  // 16384

    leftpool_kernel<<<blocks, threads>>>(
        (const float4*)x, (float4*)out, q);
}

// round 16
// speedup vs baseline: 1.0598x; 1.0004x over previous
#include <cuda_runtime.h>
#include <cuda_bf16.h>
#include <cstdint>

// LeftPool: out[b,c,h,w] = max(x[b,c,h,w:]) — reverse cummax along width (=128, contiguous).
//
// FINAL FORM — verified best across R4-R15 (reproduced 4x: ~74us ncu / ~82us wall):
//  - one warp per FOUR rows strided by q = nrows/4: 4 independent 64MB-apart
//    streams per warp spread requests across LTS slices / HBM channels
//    (consecutive-rows variant regressed DRAM 82.6% -> 77.2%, R10)
//  - front-batched float4 loads (MLP=4/thread): ILP 1->2 gave +6% BW (R5,
//    reproduced); ILP=4 saturates at the HBM 1:1 R/W-stream ceiling (~6.5 TB/s
//    kernel-average, >=90% of achievable DRAM-bus rate after turnaround)
//  - 4 independent suffix-scan chains interleave to hide SHFL latency (26cyc)
//  - 256-thread blocks, 16384 CTAs, 32 regs, ~82% occupancy
//  - rejected by experiment: streaming hints (neutral), persistent CTAs
//    (regs 32->64, occ 46%, -10% BW), 512-thread blocks (neutral)
//  - ncu metric deltas <6% on identical binaries are run-to-run clock noise (R13)

__global__ void __launch_bounds__(256) leftpool_kernel(
    const float4* __restrict__ x, float4* __restrict__ out, int q)
{
    const int gwarp = (int)((blockIdx.x * blockDim.x + threadIdx.x) >> 5);
    const int lane  = threadIdx.x & 31;
    if (gwarp >= q) return;

    const size_t stride = (size_t)q * 32;
    const size_t b0 = (size_t)gwarp * 32 + lane;     // float4 index, row g
    const size_t b1 = b0 + stride;
    const size_t b2 = b1 + stride;
    const size_t b3 = b2 + stride;

    // Front-batch all loads before any dependent work.
    float4 v0 = x[b0];
    float4 v1 = x[b1];
    float4 v2 = x[b2];
    float4 v3 = x[b3];

    // In-lane suffix max (4 independent chains).
    v0.z = fmaxf(v0.z, v0.w);  v1.z = fmaxf(v1.z, v1.w);
    v2.z = fmaxf(v2.z, v2.w);  v3.z = fmaxf(v3.z, v3.w);
    v0.y = fmaxf(v0.y, v0.z);  v1.y = fmaxf(v1.y, v1.z);
    v2.y = fmaxf(v2.y, v2.z);  v3.y = fmaxf(v3.y, v3.z);
    v0.x = fmaxf(v0.x, v0.y);  v1.x = fmaxf(v1.x, v1.y);
    v2.x = fmaxf(v2.x, v2.y);  v3.x = fmaxf(v3.x, v3.y);

    // Inclusive suffix max across lanes; 4 chains in parallel.
    float m0 = v0.x, m1 = v1.x, m2 = v2.x, m3 = v3.x;
    #pragma unroll
    for (int d = 1; d < 32; d <<= 1) {
        float t0 = __shfl_down_sync(0xffffffffu, m0, d);
        float t1 = __shfl_down_sync(0xffffffffu, m1, d);
        float t2 = __shfl_down_sync(0xffffffffu, m2, d);
        float t3 = __shfl_down_sync(0xffffffffu, m3, d);
        m0 = fmaxf(m0, t0);   // out-of-range shfl returns own value -> harmless
        m1 = fmaxf(m1, t1);
        m2 = fmaxf(m2, t2);
        m3 = fmaxf(m3, t3);
    }
    // Exclusive suffix: shift down by one; lane 31 sees -inf.
    float s0 = __shfl_down_sync(0xffffffffu, m0, 1);
    float s1 = __shfl_down_sync(0xffffffffu, m1, 1);
    float s2 = __shfl_down_sync(0xffffffffu, m2, 1);
    float s3 = __shfl_down_sync(0xffffffffu, m3, 1);
    if (lane == 31) {
        const float ninf = __int_as_float(0xff800000u);
        s0 = ninf; s1 = ninf; s2 = ninf; s3 = ninf;
    }

    v0.x = fmaxf(v0.x, s0);  v1.x = fmaxf(v1.x, s1);
    v2.x = fmaxf(v2.x, s2);  v3.x = fmaxf(v3.x, s3);
    v0.y = fmaxf(v0.y, s0);  v1.y = fmaxf(v1.y, s1);
    v2.y = fmaxf(v2.y, s2);  v3.y = fmaxf(v3.y, s3);
    v0.z = fmaxf(v0.z, s0);  v1.z = fmaxf(v1.z, s1);
    v2.z = fmaxf(v2.z, s2);  v3.z = fmaxf(v3.z, s3);
    v0.w = fmaxf(v0.w, s0);  v1.w = fmaxf(v1.w, s1);
    v2.w = fmaxf(v2.w, s2);  v3.w = fmaxf(v3.w, s3);

    out[b0] = v0;
    out[b1] = v1;
    out[b2] = v2;
    out[b3] = v3;
}

extern "C" void kernel_launch(void* const* d_in, const int* in_sizes, int n_in,
                              void* d_out, int out_size)
{
    const float* x = (const float*)d_in[0];
    float* out = (float*)d_out;

    const int W = 128;                          // contiguous width axis
    const int nrows = in_sizes[0] / W;          // 524288
    const int q = nrows / 4;                    // 131072 warps, 4 rows each

    const int threads = 256;                    // 8 warps/block
    const int warps_per_block = threads / 32;
    const int blocks = (q + warps_per_block - 1) / warps_per_block;  // 16384

    leftpool_kernel<<<blocks, threads>>>(
        (const float4*)x, (float4*)out, q);
}